// round 2
// baseline (speedup 1.0000x reference)
#include <cuda_runtime.h>

#define N 8192
#define H 512
#define SCALE 0.044194173824159216f   // 1/sqrt(512)
#define SHIFT 50.0f

// Scratch (device globals; no allocation allowed)
__device__ float g_khT[H * N];   // kh transposed: [h][node]
__device__ float g_vh[N * H];    // vh row-major: [node][h]
__device__ int   g_bucket[N];

// ---------------------------------------------------------------------------
// Producer: kh = X@kW (stored transposed), vh = X@vW (row-major)
// BM=64, BN=128, BK=16, 128 threads, 8x8 register tiles.
// ---------------------------------------------------------------------------
__global__ __launch_bounds__(128) void producer_kernel(const float* __restrict__ A,
                                                       const float* __restrict__ kW,
                                                       const float* __restrict__ vW) {
    const float* B = blockIdx.z ? vW : kW;
    __shared__ float At[16][64];    // k-major A chunk
    __shared__ float Bt[16][128];   // k-major B chunk
    int t = threadIdx.x;
    int tx = t & 15, ty = t >> 4;           // 16 x 8
    int r0 = blockIdx.x * 64, c0 = blockIdx.y * 128;

    float acc[8][8];
#pragma unroll
    for (int i = 0; i < 8; i++)
#pragma unroll
        for (int j = 0; j < 8; j++) acc[i][j] = 0.f;

    for (int kk = 0; kk < H; kk += 16) {
#pragma unroll
        for (int x = 0; x < 2; x++) {       // 64x16 A elements, transpose on store
            int fid = t + x * 128;
            int r = fid >> 2, c4 = fid & 3;
            float4 v = *(const float4*)&A[(r0 + r) * H + kk + c4 * 4];
            At[c4 * 4 + 0][r] = v.x; At[c4 * 4 + 1][r] = v.y;
            At[c4 * 4 + 2][r] = v.z; At[c4 * 4 + 3][r] = v.w;
        }
#pragma unroll
        for (int x = 0; x < 4; x++) {       // 16x128 B elements (already k-major)
            int fid = t + x * 128;
            int k = fid >> 5, cv = fid & 31;
            *(float4*)&Bt[k][cv * 4] = *(const float4*)&B[(kk + k) * 512 + c0 + cv * 4];
        }
        __syncthreads();
#pragma unroll
        for (int k = 0; k < 16; k++) {
            float a[8], b[8];
            *(float4*)(a)     = *(float4*)&At[k][ty * 8];
            *(float4*)(a + 4) = *(float4*)&At[k][ty * 8 + 4];
            *(float4*)(b)     = *(float4*)&Bt[k][tx * 8];
            *(float4*)(b + 4) = *(float4*)&Bt[k][tx * 8 + 4];
#pragma unroll
            for (int i = 0; i < 8; i++)
#pragma unroll
                for (int j = 0; j < 8; j++) acc[i][j] = fmaf(a[i], b[j], acc[i][j]);
        }
        __syncthreads();
    }

    if (blockIdx.z == 0) {
        // store kh transposed: khT[hout][node]
#pragma unroll
        for (int i = 0; i < 8; i++)
#pragma unroll
            for (int j = 0; j < 8; j++)
                g_khT[(c0 + tx * 8 + j) * N + r0 + ty * 8 + i] = acc[i][j];
    } else {
        // store vh row-major: vh[node][hout]
#pragma unroll
        for (int i = 0; i < 8; i++) {
            float4 v0 = make_float4(acc[i][0], acc[i][1], acc[i][2], acc[i][3]);
            float4 v1 = make_float4(acc[i][4], acc[i][5], acc[i][6], acc[i][7]);
            int base = (r0 + ty * 8 + i) * H + c0 + tx * 8;
            *(float4*)&g_vh[base]     = v0;
            *(float4*)&g_vh[base + 4] = v1;
        }
    }
}

// ---------------------------------------------------------------------------
// LSH bucket: rv_b = kh[n]·rot[:,b]; bucket = argmax(v0, v1, -v0, -v1)
// ---------------------------------------------------------------------------
__global__ void bucket_kernel(const float* __restrict__ rot) {
    int n = blockIdx.x * 256 + threadIdx.x;
    float v0 = 0.f, v1 = 0.f;
#pragma unroll 8
    for (int h = 0; h < H; h++) {
        float k = g_khT[h * N + n];
        v0 = fmaf(k, rot[h * 2 + 0], v0);
        v1 = fmaf(k, rot[h * 2 + 1], v1);
    }
    float best = v0; int b = 0;
    if (v1  > best) { best = v1;  b = 1; }
    if (-v0 > best) { best = -v0; b = 2; }
    if (-v1 > best) {             b = 3; }
    g_bucket[n] = b;
}

// ---------------------------------------------------------------------------
// Fused attention: per 64-row CTA, loop over 128-col tiles.
//   S = khQ @ khKᵀ * scale; mask (same bucket & adj); p = exp(s - 50)
//   l += rowsum(p); O += p @ V.  Final: out = elu(O / l).
// Single-pass softmax via fixed shift (scores bounded in [-15, 56]).
// ---------------------------------------------------------------------------
__global__ __launch_bounds__(128) void attn_kernel(const int* __restrict__ adj,
                                                   float* __restrict__ out) {
    extern __shared__ float sm[];
    float* Os   = sm;                  // [64][520]
    float* Ps   = Os + 64 * 520;       // [64][132]
    float* Qt   = Ps + 64 * 132;       // [16][64]
    float* Kt   = Qt + 16 * 64;        // [16][128]
    float* Vs   = Kt + 16 * 128;       // [16][132]
    float* lrow = Vs + 16 * 132;       // [64]
    int*   br   = (int*)(lrow + 64);   // [64]
    int*   bc   = (int*)(br + 64);     // [128]

    int t = threadIdx.x;
    int tx = t & 15, ty = t >> 4;
    int row0 = blockIdx.x * 64;

    for (int i = t; i < 64 * 520; i += 128) Os[i] = 0.f;
    if (t < 64) { lrow[t] = 0.f; br[t] = g_bucket[row0 + t]; }
    __syncthreads();

    int rb[8];
#pragma unroll
    for (int i = 0; i < 8; i++) rb[i] = br[ty * 8 + i];

    for (int jt = 0; jt < N / 128; jt++) {
        int col0 = jt * 128;
        bc[t] = g_bucket[col0 + t];
        __syncthreads();

        // ---- GEMM1: S[64x128] = Q @ K^T (K dim = H, BK=16) ----
        float s[8][8];
#pragma unroll
        for (int i = 0; i < 8; i++)
#pragma unroll
            for (int j = 0; j < 8; j++) s[i][j] = 0.f;

        for (int kk = 0; kk < H; kk += 16) {
#pragma unroll
            for (int x = 0; x < 2; x++) {
                int fid = t + x * 128;
                int k = fid >> 4, rv = fid & 15;
                *(float4*)&Qt[k * 64 + rv * 4] =
                    *(const float4*)&g_khT[(kk + k) * N + row0 + rv * 4];
            }
#pragma unroll
            for (int x = 0; x < 4; x++) {
                int fid = t + x * 128;
                int k = fid >> 5, cv = fid & 31;
                *(float4*)&Kt[k * 128 + cv * 4] =
                    *(const float4*)&g_khT[(kk + k) * N + col0 + cv * 4];
            }
            __syncthreads();
#pragma unroll
            for (int k = 0; k < 16; k++) {
                float a[8], b[8];
                *(float4*)(a)     = *(float4*)&Qt[k * 64 + ty * 8];
                *(float4*)(a + 4) = *(float4*)&Qt[k * 64 + ty * 8 + 4];
                *(float4*)(b)     = *(float4*)&Kt[k * 128 + tx * 8];
                *(float4*)(b + 4) = *(float4*)&Kt[k * 128 + tx * 8 + 4];
#pragma unroll
                for (int i = 0; i < 8; i++)
#pragma unroll
                    for (int j = 0; j < 8; j++) s[i][j] = fmaf(a[i], b[j], s[i][j]);
            }
            __syncthreads();
        }

        // ---- mask + exp -> Ps ----
#pragma unroll
        for (int i = 0; i < 8; i++) {
            int grow = row0 + ty * 8 + i;
            const int4 a0 = *(const int4*)&adj[grow * N + col0 + tx * 8];
            const int4 a1 = *(const int4*)&adj[grow * N + col0 + tx * 8 + 4];
            int av[8] = {a0.x, a0.y, a0.z, a0.w, a1.x, a1.y, a1.z, a1.w};
            float p[8];
#pragma unroll
            for (int j = 0; j < 8; j++) {
                bool valid = (rb[i] == bc[tx * 8 + j]) && (av[j] > 0);
                p[j] = valid ? __expf(fmaf(s[i][j], SCALE, -SHIFT)) : 0.f;
            }
            int base = (ty * 8 + i) * 132 + tx * 8;
            *(float4*)&Ps[base]     = make_float4(p[0], p[1], p[2], p[3]);
            *(float4*)&Ps[base + 4] = make_float4(p[4], p[5], p[6], p[7]);
        }
        __syncthreads();

        // ---- row-sum of p into l ----
        if (t < 64) {
            float acc = 0.f;
#pragma unroll 8
            for (int j = 0; j < 128; j++) acc += Ps[t * 132 + j];
            lrow[t] += acc;
        }

        // ---- GEMM2: O[64x512] += P[64x128] @ V[128x512] ----
#pragma unroll 1
        for (int hp = 0; hp < 4; hp++) {
            float c[8][8];
#pragma unroll
            for (int i = 0; i < 8; i++) {
                int base = (ty * 8 + i) * 520 + hp * 128 + tx * 8;
                *(float4*)&c[i][0] = *(float4*)&Os[base];
                *(float4*)&c[i][4] = *(float4*)&Os[base + 4];
            }
#pragma unroll 1
            for (int jc = 0; jc < 8; jc++) {
                __syncthreads();
#pragma unroll
                for (int x = 0; x < 4; x++) {
                    int fid = t + x * 128;
                    int r = fid >> 5, cv = fid & 31;
                    *(float4*)&Vs[r * 132 + cv * 4] =
                        *(const float4*)&g_vh[(col0 + jc * 16 + r) * H + hp * 128 + cv * 4];
                }
                __syncthreads();
#pragma unroll
                for (int k = 0; k < 16; k++) {
                    float b[8];
                    *(float4*)&b[0] = *(float4*)&Vs[k * 132 + tx * 8];
                    *(float4*)&b[4] = *(float4*)&Vs[k * 132 + tx * 8 + 4];
                    int jj = jc * 16 + k;
#pragma unroll
                    for (int i = 0; i < 8; i++) {
                        float a = Ps[(ty * 8 + i) * 132 + jj];
#pragma unroll
                        for (int j = 0; j < 8; j++) c[i][j] = fmaf(a, b[j], c[i][j]);
                    }
                }
            }
#pragma unroll
            for (int i = 0; i < 8; i++) {
                int base = (ty * 8 + i) * 520 + hp * 128 + tx * 8;
                *(float4*)&Os[base]     = *(float4*)&c[i][0];
                *(float4*)&Os[base + 4] = *(float4*)&c[i][4];
            }
        }
        __syncthreads();
    }

    // ---- epilogue: normalize + ELU + store ----
#pragma unroll 1
    for (int x = 0; x < 64; x++) {
        int fid = t + x * 128;
        int r = fid >> 7, cv = fid & 127;
        float inv = 1.f / lrow[r];
        float4 v = *(float4*)&Os[r * 520 + cv * 4];
        v.x *= inv; v.y *= inv; v.z *= inv; v.w *= inv;
        v.x = v.x > 0.f ? v.x : expm1f(v.x);
        v.y = v.y > 0.f ? v.y : expm1f(v.y);
        v.z = v.z > 0.f ? v.z : expm1f(v.z);
        v.w = v.w > 0.f ? v.w : expm1f(v.w);
        *(float4*)&out[(row0 + r) * H + cv * 4] = v;
    }
}

// ---------------------------------------------------------------------------
extern "C" void kernel_launch(void* const* d_in, const int* in_sizes, int n_in,
                              void* d_out, int out_size) {
    const float* input = (const float*)d_in[0];
    const int*   adj   = (const int*)d_in[1];
    const float* rot   = (const float*)d_in[2];
    const float* kW    = (const float*)d_in[3];
    const float* vW    = (const float*)d_in[4];
    float* out = (float*)d_out;

    const int smem_bytes = (64 * 520 + 64 * 132 + 16 * 64 + 16 * 128 + 16 * 132
                            + 64 + 64 + 128) * 4;
    cudaFuncSetAttribute(attn_kernel, cudaFuncAttributeMaxDynamicSharedMemorySize,
                         smem_bytes);

    producer_kernel<<<dim3(N / 64, H / 128, 2), 128>>>(input, kW, vW);
    bucket_kernel<<<N / 256, 256>>>(rot);
    attn_kernel<<<N / 64, 128, smem_bytes>>>(adj, out);
}

// round 3
// speedup vs baseline: 3.2867x; 3.2867x over previous
#include <cuda_runtime.h>

#define N 8192
#define H 512
#define SCALE 0.044194173824159216f   // 1/sqrt(512)
#define SHIFT 50.0f

// Scratch (device globals; no allocation allowed)
__device__ float g_khT[H * N];    // kh transposed: [h][node] (original order)
__device__ float g_vh[N * H];     // vh row-major (original order)
__device__ float g_khTs[H * N];   // kh transposed, sorted node order
__device__ float g_vhp[N * H];    // vh row-major, sorted node order
__device__ int   g_bucket[N];     // bucket per original node
__device__ int   g_perm[N];       // sorted pos -> original node
__device__ int   g_bsorted[N];    // bucket per sorted pos
__device__ int   g_chist[32 * 4]; // per-chunk bucket histogram
__device__ int   g_bstart[5];     // bucket start offsets in sorted order

// ---------------------------------------------------------------------------
// Producer: kh = X@kW (stored transposed), vh = X@vW (row-major)
// ---------------------------------------------------------------------------
__global__ __launch_bounds__(128) void producer_kernel(const float* __restrict__ A,
                                                       const float* __restrict__ kW,
                                                       const float* __restrict__ vW) {
    const float* B = blockIdx.z ? vW : kW;
    __shared__ float At[16][64];
    __shared__ float Bt[16][128];
    int t = threadIdx.x;
    int tx = t & 15, ty = t >> 4;
    int r0 = blockIdx.x * 64, c0 = blockIdx.y * 128;

    float acc[8][8];
#pragma unroll
    for (int i = 0; i < 8; i++)
#pragma unroll
        for (int j = 0; j < 8; j++) acc[i][j] = 0.f;

    for (int kk = 0; kk < H; kk += 16) {
#pragma unroll
        for (int x = 0; x < 2; x++) {
            int fid = t + x * 128;
            int r = fid >> 2, c4 = fid & 3;
            float4 v = *(const float4*)&A[(r0 + r) * H + kk + c4 * 4];
            At[c4 * 4 + 0][r] = v.x; At[c4 * 4 + 1][r] = v.y;
            At[c4 * 4 + 2][r] = v.z; At[c4 * 4 + 3][r] = v.w;
        }
#pragma unroll
        for (int x = 0; x < 4; x++) {
            int fid = t + x * 128;
            int k = fid >> 5, cv = fid & 31;
            *(float4*)&Bt[k][cv * 4] = *(const float4*)&B[(kk + k) * 512 + c0 + cv * 4];
        }
        __syncthreads();
#pragma unroll
        for (int k = 0; k < 16; k++) {
            float a[8], b[8];
            *(float4*)(a)     = *(float4*)&At[k][ty * 8];
            *(float4*)(a + 4) = *(float4*)&At[k][ty * 8 + 4];
            *(float4*)(b)     = *(float4*)&Bt[k][tx * 8];
            *(float4*)(b + 4) = *(float4*)&Bt[k][tx * 8 + 4];
#pragma unroll
            for (int i = 0; i < 8; i++)
#pragma unroll
                for (int j = 0; j < 8; j++) acc[i][j] = fmaf(a[i], b[j], acc[i][j]);
        }
        __syncthreads();
    }

    if (blockIdx.z == 0) {
#pragma unroll
        for (int i = 0; i < 8; i++)
#pragma unroll
            for (int j = 0; j < 8; j++)
                g_khT[(c0 + tx * 8 + j) * N + r0 + ty * 8 + i] = acc[i][j];
    } else {
#pragma unroll
        for (int i = 0; i < 8; i++) {
            int base = (r0 + ty * 8 + i) * H + c0 + tx * 8;
            *(float4*)&g_vh[base]     = make_float4(acc[i][0], acc[i][1], acc[i][2], acc[i][3]);
            *(float4*)&g_vh[base + 4] = make_float4(acc[i][4], acc[i][5], acc[i][6], acc[i][7]);
        }
    }
}

// ---------------------------------------------------------------------------
// LSH bucket
// ---------------------------------------------------------------------------
__global__ void bucket_kernel(const float* __restrict__ rot) {
    int n = blockIdx.x * 256 + threadIdx.x;
    float v0 = 0.f, v1 = 0.f;
#pragma unroll 8
    for (int h = 0; h < H; h++) {
        float k = g_khT[h * N + n];
        v0 = fmaf(k, rot[h * 2 + 0], v0);
        v1 = fmaf(k, rot[h * 2 + 1], v1);
    }
    float best = v0; int b = 0;
    if (v1  > best) { best = v1;  b = 1; }
    if (-v0 > best) { best = -v0; b = 2; }
    if (-v1 > best) {             b = 3; }
    g_bucket[n] = b;
}

// ---------------------------------------------------------------------------
// Stable counting sort by bucket: hist -> scatter (deterministic)
// ---------------------------------------------------------------------------
__global__ void hist_kernel() {
    __shared__ int h[4];
    int t = threadIdx.x;
    if (t < 4) h[t] = 0;
    __syncthreads();
    atomicAdd(&h[g_bucket[blockIdx.x * 256 + t]], 1);
    __syncthreads();
    if (t < 4) g_chist[blockIdx.x * 4 + t] = h[t];
}

__global__ void scatter_kernel() {
    __shared__ int lb[256];
    __shared__ int chs[128];
    int t = threadIdx.x, c = blockIdx.x;
    int node = c * 256 + t;
    int b = g_bucket[node];
    lb[t] = b;
    if (t < 128) chs[t] = g_chist[t];
    __syncthreads();

    int tot[4] = {0, 0, 0, 0};
    int pri = 0;
    for (int cc = 0; cc < 32; cc++) {
        if (cc < c) pri += chs[cc * 4 + b];
        tot[0] += chs[cc * 4 + 0]; tot[1] += chs[cc * 4 + 1];
        tot[2] += chs[cc * 4 + 2]; tot[3] += chs[cc * 4 + 3];
    }
    int bs = 0;
    for (int bb = 0; bb < 4; bb++) if (bb < b) bs += tot[bb];
    int r = 0;
    for (int j = 0; j < t; j++) r += (lb[j] == b);
    int pos = bs + pri + r;
    g_perm[pos] = node;
    g_bsorted[pos] = b;

    if (c == 0 && t < 4) {
        int s = 0;
        for (int bb = 0; bb < t; bb++) s += tot[bb];
        g_bstart[t] = s;
        if (t == 0) g_bstart[4] = N;
    }
}

// ---------------------------------------------------------------------------
// Permute kh/vh into sorted order
// ---------------------------------------------------------------------------
__global__ void permute_khT_kernel() {
    int idx = blockIdx.x * 256 + threadIdx.x;   // over H*N
    int h = idx >> 13, pos = idx & 8191;
    g_khTs[idx] = g_khT[(h << 13) + g_perm[pos]];
}

__global__ void permute_vh_kernel() {
    int idx = blockIdx.x * 256 + threadIdx.x;   // over N*128 float4
    int pos = idx >> 7, c4 = idx & 127;
    ((float4*)g_vhp)[idx] = ((const float4*)g_vh)[g_perm[pos] * 128 + c4];
}

// ---------------------------------------------------------------------------
// Fused block-diagonal attention on sorted order.
// 256 threads, 64-row tiles, col tiles limited to this tile's bucket range.
// Thread tile: 4 rows x 8 cols (cols split as {tx*4, 64+tx*4} for
// conflict-free LDS.128).
// ---------------------------------------------------------------------------
__global__ __launch_bounds__(256) void attn_kernel(const int* __restrict__ adj,
                                                   float* __restrict__ out) {
    extern __shared__ float sm[];
    float* Os   = sm;                  // [64][520]
    float* Ps   = Os + 64 * 520;       // [64][132]
    float* Qt   = Ps + 64 * 132;       // [16][64]
    float* Kt   = Qt + 16 * 64;        // [16][128]
    float* Vs   = Kt + 16 * 128;       // [16][132]
    float* lrow = Vs + 16 * 132;       // [64]
    int*   br   = (int*)(lrow + 64);   // [64]
    int*   pr   = br + 64;             // [64]  original row ids
    int*   bc   = pr + 64;             // [128]
    int*   pc   = bc + 128;            // [128] original col ids

    int t = threadIdx.x;
    int tx = t & 15, ty = t >> 4;      // 16 x 16
    int row0 = blockIdx.x * 64;

    for (int i = t; i < 64 * 520; i += 256) Os[i] = 0.f;
    if (t < 64) {
        lrow[t] = 0.f;
        br[t] = g_bsorted[row0 + t];
        pr[t] = g_perm[row0 + t];
    }
    __syncthreads();

    int rb[4];
#pragma unroll
    for (int i = 0; i < 4; i++) rb[i] = br[ty * 4 + i];

    int b_lo = g_bsorted[row0];
    int b_hi = g_bsorted[row0 + 63];
    int cstart = g_bstart[b_lo];
    int cend   = g_bstart[b_hi + 1];

    for (int col0 = cstart & ~127; col0 < cend; col0 += 128) {
        if (t < 128) {
            bc[t] = g_bsorted[col0 + t];
            pc[t] = g_perm[col0 + t];
        }
        __syncthreads();

        // ---- GEMM1: S[64x128] = Q @ K^T ----
        float s[4][8];
#pragma unroll
        for (int i = 0; i < 4; i++)
#pragma unroll
            for (int j = 0; j < 8; j++) s[i][j] = 0.f;

        for (int kk = 0; kk < H; kk += 16) {
            {   // Qt: 16x64, 1 float4/thread
                int k = t >> 4, rv = t & 15;
                *(float4*)&Qt[k * 64 + rv * 4] =
                    *(const float4*)&g_khTs[(kk + k) * N + row0 + rv * 4];
            }
#pragma unroll
            for (int x = 0; x < 2; x++) {   // Kt: 16x128, 2 float4/thread
                int fid = t + x * 256;
                int k = fid >> 5, cv = fid & 31;
                *(float4*)&Kt[k * 128 + cv * 4] =
                    *(const float4*)&g_khTs[(kk + k) * N + col0 + cv * 4];
            }
            __syncthreads();
#pragma unroll
            for (int k = 0; k < 16; k++) {
                float a[4], b[8];
                *(float4*)(a)     = *(float4*)&Qt[k * 64 + ty * 4];
                *(float4*)(b)     = *(float4*)&Kt[k * 128 + tx * 4];
                *(float4*)(b + 4) = *(float4*)&Kt[k * 128 + 64 + tx * 4];
#pragma unroll
                for (int i = 0; i < 4; i++)
#pragma unroll
                    for (int j = 0; j < 8; j++) s[i][j] = fmaf(a[i], b[j], s[i][j]);
            }
            __syncthreads();
        }

        // ---- mask (same bucket & adj) + exp -> Ps ----
#pragma unroll
        for (int i = 0; i < 4; i++) {
            int rowbase = pr[ty * 4 + i] * N;
            float p[8];
#pragma unroll
            for (int j = 0; j < 8; j++) {
                int cidx = (j < 4) ? (tx * 4 + j) : (64 + tx * 4 + j - 4);
                int av = __ldg(&adj[rowbase + pc[cidx]]);
                bool valid = (rb[i] == bc[cidx]) && (av > 0);
                p[j] = valid ? __expf(fmaf(s[i][j], SCALE, -SHIFT)) : 0.f;
            }
            int base = (ty * 4 + i) * 132;
            *(float4*)&Ps[base + tx * 4]      = make_float4(p[0], p[1], p[2], p[3]);
            *(float4*)&Ps[base + 64 + tx * 4] = make_float4(p[4], p[5], p[6], p[7]);
        }
        __syncthreads();

        // ---- row-sum of p into l ----
        if (t < 64) {
            float acc = 0.f;
#pragma unroll 8
            for (int j = 0; j < 128; j++) acc += Ps[t * 132 + j];
            lrow[t] += acc;
        }

        // ---- GEMM2: O[64x512] += P[64x128] @ V[128x512] ----
#pragma unroll 1
        for (int hp = 0; hp < 4; hp++) {
            float c[4][8];
#pragma unroll
            for (int i = 0; i < 4; i++) {
                int base = (ty * 4 + i) * 520 + hp * 128;
                *(float4*)&c[i][0] = *(float4*)&Os[base + tx * 4];
                *(float4*)&c[i][4] = *(float4*)&Os[base + 64 + tx * 4];
            }
#pragma unroll 1
            for (int jc = 0; jc < 8; jc++) {
                __syncthreads();
#pragma unroll
                for (int x = 0; x < 2; x++) {
                    int fid = t + x * 256;
                    int r = fid >> 5, cv = fid & 31;
                    *(float4*)&Vs[r * 132 + cv * 4] =
                        *(const float4*)&g_vhp[(col0 + jc * 16 + r) * H + hp * 128 + cv * 4];
                }
                __syncthreads();
#pragma unroll
                for (int k = 0; k < 16; k++) {
                    float b[8];
                    *(float4*)&b[0] = *(float4*)&Vs[k * 132 + tx * 4];
                    *(float4*)&b[4] = *(float4*)&Vs[k * 132 + 64 + tx * 4];
                    int jj = jc * 16 + k;
#pragma unroll
                    for (int i = 0; i < 4; i++) {
                        float a = Ps[(ty * 4 + i) * 132 + jj];
#pragma unroll
                        for (int j = 0; j < 8; j++) c[i][j] = fmaf(a, b[j], c[i][j]);
                    }
                }
            }
#pragma unroll
            for (int i = 0; i < 4; i++) {
                int base = (ty * 4 + i) * 520 + hp * 128;
                *(float4*)&Os[base + tx * 4]      = *(float4*)&c[i][0];
                *(float4*)&Os[base + 64 + tx * 4] = *(float4*)&c[i][4];
            }
        }
        __syncthreads();
    }

    // ---- epilogue: normalize + ELU + scatter rows to original order ----
#pragma unroll 1
    for (int x = 0; x < 32; x++) {
        int fid = t + x * 256;
        int r = fid >> 7, cv = fid & 127;
        float inv = 1.f / lrow[r];
        float4 v = *(float4*)&Os[r * 520 + cv * 4];
        v.x *= inv; v.y *= inv; v.z *= inv; v.w *= inv;
        v.x = v.x > 0.f ? v.x : expm1f(v.x);
        v.y = v.y > 0.f ? v.y : expm1f(v.y);
        v.z = v.z > 0.f ? v.z : expm1f(v.z);
        v.w = v.w > 0.f ? v.w : expm1f(v.w);
        *(float4*)&out[pr[r] * H + cv * 4] = v;
    }
}

// ---------------------------------------------------------------------------
extern "C" void kernel_launch(void* const* d_in, const int* in_sizes, int n_in,
                              void* d_out, int out_size) {
    const float* input = (const float*)d_in[0];
    const int*   adj   = (const int*)d_in[1];
    const float* rot   = (const float*)d_in[2];
    const float* kW    = (const float*)d_in[3];
    const float* vW    = (const float*)d_in[4];
    float* out = (float*)d_out;

    const int smem_bytes = (64 * 520 + 64 * 132 + 16 * 64 + 16 * 128 + 16 * 132
                            + 64 + 64 + 64 + 128 + 128) * 4;
    cudaFuncSetAttribute(attn_kernel, cudaFuncAttributeMaxDynamicSharedMemorySize,
                         smem_bytes);

    producer_kernel<<<dim3(N / 64, H / 128, 2), 128>>>(input, kW, vW);
    bucket_kernel<<<N / 256, 256>>>(rot);
    hist_kernel<<<32, 256>>>();
    scatter_kernel<<<32, 256>>>();
    permute_khT_kernel<<<H * N / 256, 256>>>();
    permute_vh_kernel<<<N * 128 / 256, 256>>>();
    attn_kernel<<<N / 64, 256, smem_bytes>>>(adj, out);
}